// round 3
// baseline (speedup 1.0000x reference)
#include <cuda_runtime.h>
#include <cstdint>

// Problem constants (fixed by reference setup_inputs)
#define BB   16
#define NN   1000
#define KK   50
#define DD   128
#define NPOW 1024
#define NTHREADS 256

// Output layout (float32, concatenation of reference outputs):
//   [0,                2048000)  x            = init_embeddings
//   [2048000,          2848000)  edge_index row 0 (src)
//   [2848000,          3648000)  edge_index row 1 (dst)
//   [3648000,        106048000)  edge_emb [B*n*k, D]
#define X_ELEMS   (BB * NN * DD)          // 2,048,000
#define E_ELEMS   (BB * NN * KK)          // 800,000

__global__ __launch_bounds__(NTHREADS)
void tsp_edge_kernel(const float* __restrict__ locs,   // [B, N, 2]
                     const float* __restrict__ W,      // [128] (shape (1,128))
                     const float* __restrict__ bias,   // [128]
                     float* __restrict__ out)
{
    __shared__ unsigned long long keys[NPOW];   // 8 KB
    __shared__ float2 sloc[NN];                 // 8 KB
    __shared__ float  sdist[KK];

    const int row = blockIdx.x;          // b * NN + i
    const int b   = row / NN;
    const int i   = row - b * NN;
    const int tid = threadIdx.x;

    // Stage batch's locations in smem (hot in L2 across the 1000 blocks per batch).
    const float2* locb = reinterpret_cast<const float2*>(locs + (size_t)b * NN * 2);
    for (int t = tid; t < NN; t += NTHREADS) sloc[t] = locb[t];
    __syncthreads();

    const float2 my = sloc[i];

    // Build sort keys: (dist_bits << 10) | idx. Ascending u64 sort ==
    // ascending distance with ties broken by lower index (matches lax.top_k).
    for (int t = tid; t < NPOW; t += NTHREADS) {
        unsigned long long key = 0xFFFFFFFFFFFFFFFFull;  // pad / self-loop sentinel
        if (t < NN && t != i) {
            float dx = my.x - sloc[t].x;
            float dy = my.y - sloc[t].y;
            // Match jax f32 arithmetic exactly; forbid fma contraction.
            float d2 = __fadd_rn(__fadd_rn(__fmul_rn(dx, dx), __fmul_rn(dy, dy)),
                                 1e-12f);
            float d  = __fsqrt_rn(d2);   // IEEE sqrt regardless of fast-math flags
            key = ((unsigned long long)__float_as_uint(d) << 10) | (unsigned)t;
        }
        keys[t] = key;
    }
    __syncthreads();

    // Bitonic sort of 1024 u64 keys, ascending. Pairs within one (k,j) step are
    // disjoint, so no sync is needed inside the per-element loop.
    for (int k = 2; k <= NPOW; k <<= 1) {
        for (int j = k >> 1; j > 0; j >>= 1) {
            for (int t = tid; t < NPOW; t += NTHREADS) {
                int ixj = t ^ j;
                if (ixj > t) {
                    unsigned long long a = keys[t];
                    unsigned long long c = keys[ixj];
                    bool up = ((t & k) == 0);
                    if ((a > c) == up) { keys[t] = c; keys[ixj] = a; }
                }
            }
            __syncthreads();
        }
    }

    // Emit edge_index (as float) and stage the 50 distances.
    if (tid < KK) {
        unsigned long long key = keys[tid];
        float d  = __uint_as_float((unsigned int)(key >> 10));
        int   nb = (int)(key & 1023u);
        sdist[tid] = d;

        const long long e = (long long)row * KK + tid;
        float* src = out + X_ELEMS;
        float* dst = src + E_ELEMS;
        src[e] = (float)(b * NN + i);
        dst[e] = (float)(b * NN + nb);
    }
    __syncthreads();

    // edge_emb[e, d] = dist_e * W[d] + bias[d]; two rows in flight per iteration,
    // each 512B row written coalesced by 128 consecutive threads.
    float* emb = out + X_ELEMS + 2LL * E_ELEMS;
    const int d    = tid & (DD - 1);
    const int slot = tid >> 7;                 // 0 or 1
    const float w  = __ldg(W + d);
    const float bv = __ldg(bias + d);
    const long long base = (long long)row * KK;
    #pragma unroll 5
    for (int s = slot; s < KK; s += (NTHREADS / DD)) {
        emb[(base + s) * DD + d] = fmaf(sdist[s], w, bv);
    }
}

extern "C" void kernel_launch(void* const* d_in, const int* in_sizes, int n_in,
                              void* d_out, int out_size)
{
    const float* locs = (const float*)d_in[0];   // [16, 1000, 2]
    const float* xin  = (const float*)d_in[1];   // [16, 1000, 128]
    const float* W    = (const float*)d_in[2];   // [1, 128]
    const float* bias = (const float*)d_in[3];   // [128]
    float* out = (float*)d_out;

    // x output = straight copy of init_embeddings (async D2D is capturable).
    cudaMemcpyAsync(out, xin, (size_t)X_ELEMS * sizeof(float),
                    cudaMemcpyDeviceToDevice, 0);

    tsp_edge_kernel<<<BB * NN, NTHREADS, 0, 0>>>(locs, W, bias, out);
}

// round 4
// speedup vs baseline: 3.2954x; 3.2954x over previous
#include <cuda_runtime.h>
#include <cstdint>

// Problem constants (fixed by reference setup_inputs)
#define BB   16
#define NN   1000
#define KK   50
#define DD   128
#define NTHREADS 256
#define CAND_CAP 256   // candidate buffer for the final small sort

// Output layout (float32, concatenation of reference outputs):
//   [0,        2048000)   x = init_embeddings
//   [2048000,  2848000)   edge_index row 0 (src)
//   [2848000,  3648000)   edge_index row 1 (dst)
//   [3648000, 106048000)  edge_emb [B*n*k, D]
#define X_ELEMS   (BB * NN * DD)
#define E_ELEMS   (BB * NN * KK)

// Exclusive block scan over 256 per-thread values (8 warps). Two internal
// __syncthreads so wsum is safely reusable by the caller afterwards.
__device__ __forceinline__ unsigned int
block_excl_scan_256(unsigned int v, volatile unsigned int* wsum, int tid)
{
    const int lane = tid & 31, w = tid >> 5;
    unsigned int incl = v;
    #pragma unroll
    for (int o = 1; o < 32; o <<= 1) {
        unsigned int x = __shfl_up_sync(0xFFFFFFFFu, incl, o);
        if (lane >= o) incl += x;
    }
    if (lane == 31) wsum[w] = incl;
    __syncthreads();
    unsigned int base = 0;
    for (int ww = 0; ww < w; ++ww) base += wsum[ww];  // <=7 broadcast reads
    __syncthreads();
    return base + incl - v;
}

__global__ __launch_bounds__(NTHREADS)
void tsp_topk_kernel(const float* __restrict__ locs,   // [B, N, 2]
                     const float* __restrict__ W,      // [128]
                     const float* __restrict__ bias,   // [128]
                     float* __restrict__ out)
{
    __shared__ float2 sloc[NN];                         // 8000 B
    __shared__ unsigned int db[1024];                   // 4096 B (dist bits)
    __shared__ unsigned int hist[2048];                 // 8192 B
    __shared__ unsigned long long cand[CAND_CAP];       // 2048 B
    __shared__ unsigned int wsum[8];
    __shared__ unsigned int s_c1, s_less1, s_P, s_m;
    __shared__ float sdist[KK];

    const int row = blockIdx.x;          // b * NN + i
    const int b   = row / NN;
    const int i   = row - b * NN;
    const int tid = threadIdx.x;

    // Stage this batch's locations; clear level-1 histogram.
    const float2* locb = reinterpret_cast<const float2*>(locs + (size_t)b * NN * 2);
    for (int t = tid; t < NN; t += NTHREADS) sloc[t] = locb[t];
    for (int t = tid; t < 2048; t += NTHREADS) hist[t] = 0;
    if (tid == 0) s_m = 0;
    __syncthreads();

    const float2 my = sloc[i];

    // Distance bits (monotone key: d >= 0 so float bits order == value order).
    // Self-loop and pad slots get 0xFFFFFFFF (never selected: k=50 < 999 real).
    for (int t = tid; t < 1024; t += NTHREADS) {
        unsigned int v = 0xFFFFFFFFu;
        if (t < NN && t != i) {
            float dx = my.x - sloc[t].x;
            float dy = my.y - sloc[t].y;
            // Match jax f32 arithmetic exactly; forbid fma contraction.
            float d2 = __fadd_rn(__fadd_rn(__fmul_rn(dx, dx), __fmul_rn(dy, dy)),
                                 1e-12f);
            v = __float_as_uint(__fsqrt_rn(d2));
        }
        db[t] = v;
        atomicAdd(&hist[v >> 21], 1u);   // level-1: 11-bit prefix
    }
    __syncthreads();

    // Level-1 cutoff: find bin holding rank KK. Each thread owns 8 bins.
    {
        unsigned int s = 0;
        #pragma unroll
        for (int j = 0; j < 8; ++j) s += hist[tid * 8 + j];
        unsigned int e = block_excl_scan_256(s, wsum, tid);
        if (e < KK && KK <= e + s) {
            unsigned int cum = e;
            #pragma unroll
            for (int j = 0; j < 8; ++j) {
                unsigned int c = hist[tid * 8 + j];
                if (KK <= cum + c) { s_c1 = tid * 8 + j; s_less1 = cum; break; }
                cum += c;
            }
        }
    }
    __syncthreads();
    const unsigned int c1    = s_c1;
    const unsigned int less1 = s_less1;

    // Level-2 histogram over the cutoff bin (next 8 bits -> 19-bit prefix).
    hist[tid] = 0;                       // NTHREADS == 256 clears exactly
    __syncthreads();
    for (int t = tid; t < 1024; t += NTHREADS) {
        unsigned int v = db[t];
        if ((v >> 21) == c1) atomicAdd(&hist[(v >> 13) & 0xFFu], 1u);
    }
    __syncthreads();
    {
        const unsigned int K2 = KK - less1;          // >= 1
        unsigned int s = hist[tid];
        unsigned int e = block_excl_scan_256(s, wsum, tid);
        if (e < K2 && K2 <= e + s) s_P = (c1 << 8) | (unsigned)tid;
    }
    __syncthreads();
    const unsigned int P = s_P;

    // Compact all candidates with 19-bit prefix <= P (includes all ties at the
    // rank-50 boundary, so exact top-50 by full 64-bit key is inside the set).
    for (int t = tid; t < 1024; t += NTHREADS) {
        unsigned int v = db[t];
        if ((v >> 13) <= P) {
            unsigned int pos = atomicAdd(&s_m, 1u);
            if (pos < CAND_CAP)
                cand[pos] = ((unsigned long long)v << 10) | (unsigned)t;
        }
    }
    __syncthreads();
    if (tid >= (int)min(s_m, (unsigned)CAND_CAP))
        cand[tid] = 0xFFFFFFFFFFFFFFFFull;           // pad
    __syncthreads();

    // Bitonic sort of 256 u64 keys, ascending. Equal-distance ties break to
    // the lower index (low 10 bits), matching lax.top_k stability.
    for (int k = 2; k <= CAND_CAP; k <<= 1) {
        for (int j = k >> 1; j > 0; j >>= 1) {
            const int t = tid, ixj = t ^ j;
            if (ixj > t) {
                unsigned long long a = cand[t];
                unsigned long long c = cand[ixj];
                bool up = ((t & k) == 0);
                if ((a > c) == up) { cand[t] = c; cand[ixj] = a; }
            }
            __syncthreads();
        }
    }

    // Emit edge_index (as float) and stage the 50 distances.
    if (tid < KK) {
        unsigned long long key = cand[tid];
        float d  = __uint_as_float((unsigned int)(key >> 10));
        int   nb = (int)(key & 1023u);
        sdist[tid] = d;

        const long long e = (long long)row * KK + tid;
        float* src = out + X_ELEMS;
        float* dst = src + E_ELEMS;
        src[e] = (float)(b * NN + i);
        dst[e] = (float)(b * NN + nb);
    }
    __syncthreads();

    // edge_emb[e, d] = dist_e * W[d] + bias[d]; two 512B rows per iteration,
    // fully coalesced.
    float* emb = out + X_ELEMS + 2LL * E_ELEMS;
    const int d    = tid & (DD - 1);
    const int slot = tid >> 7;                 // 0 or 1
    const float w  = __ldg(W + d);
    const float bv = __ldg(bias + d);
    const long long base = (long long)row * KK;
    #pragma unroll 5
    for (int s = slot; s < KK; s += (NTHREADS / DD)) {
        emb[(base + s) * DD + d] = fmaf(sdist[s], w, bv);
    }
}

extern "C" void kernel_launch(void* const* d_in, const int* in_sizes, int n_in,
                              void* d_out, int out_size)
{
    const float* locs = (const float*)d_in[0];   // [16, 1000, 2]
    const float* xin  = (const float*)d_in[1];   // [16, 1000, 128]
    const float* W    = (const float*)d_in[2];   // [1, 128]
    const float* bias = (const float*)d_in[3];   // [128]
    float* out = (float*)d_out;

    // x output = straight copy of init_embeddings (async D2D is capturable).
    cudaMemcpyAsync(out, xin, (size_t)X_ELEMS * sizeof(float),
                    cudaMemcpyDeviceToDevice, 0);

    tsp_topk_kernel<<<BB * NN, NTHREADS, 0, 0>>>(locs, W, bias, out);
}

// round 5
// speedup vs baseline: 5.6005x; 1.6995x over previous
#include <cuda_runtime.h>
#include <cstdint>

// Problem constants (fixed by reference setup_inputs)
#define BB   16
#define NN   1000
#define KK   50
#define DD   128
#define NTHREADS 256
#define CAND_CAP 256

// Output layout (float32, concatenation of reference outputs):
//   [0,        2048000)   x = init_embeddings
//   [2048000,  2848000)   edge_index row 0 (src)
//   [2848000,  3648000)   edge_index row 1 (dst)
//   [3648000, 106048000)  edge_emb [B*n*k, D]
#define X_ELEMS   (BB * NN * DD)
#define E_ELEMS   (BB * NN * KK)

// Exclusive block scan over 256 per-thread values (8 warps). Two internal
// __syncthreads; must be called by all 256 threads.
__device__ __forceinline__ unsigned int
block_excl_scan_256(unsigned int v, volatile unsigned int* wsum, int tid)
{
    const int lane = tid & 31, w = tid >> 5;
    unsigned int incl = v;
    #pragma unroll
    for (int o = 1; o < 32; o <<= 1) {
        unsigned int x = __shfl_up_sync(0xFFFFFFFFu, incl, o);
        if (lane >= o) incl += x;
    }
    if (lane == 31) wsum[w] = incl;
    __syncthreads();
    unsigned int base = 0;
    for (int ww = 0; ww < w; ++ww) base += wsum[ww];
    __syncthreads();
    return base + incl - v;
}

__global__ __launch_bounds__(NTHREADS)
void tsp_topk_kernel(const float* __restrict__ locs,   // [B, N, 2]
                     const float* __restrict__ xin,    // [B, N, 128]
                     const float* __restrict__ W,      // [128]
                     const float* __restrict__ bias,   // [128]
                     float* __restrict__ out)
{
    __shared__ float2 sloc[NN];                        // 8000 B
    __shared__ unsigned int db2[1024];                 // 4096 B (d^2 bits)
    __shared__ unsigned int hist[256];                 // 1024 B
    __shared__ unsigned long long cand[CAND_CAP];      // 2048 B
    __shared__ unsigned int wsum[8];
    __shared__ unsigned int s_c1, s_less1, s_P, s_m;
    __shared__ float sdist[KK];

    const int row  = blockIdx.x;         // == global node index b*NN + i
    const int b    = row / NN;
    const int i    = row - b * NN;
    const int tid  = threadIdx.x;
    const int lane = tid & 31;

    // Fold the x output (copy of init_embeddings) into this kernel: one
    // 512B row per block, float4-vectorized by the first warp.
    if (tid < 32) {
        const float4* xr = reinterpret_cast<const float4*>(xin) + (size_t)row * 32;
        float4*       xo = reinterpret_cast<float4*>(out) + (size_t)row * 32;
        xo[tid] = xr[tid];
    }

    // Stage this batch's locations; clear level-1 histogram.
    const float2* locb = reinterpret_cast<const float2*>(locs + (size_t)b * NN * 2);
    for (int t = tid; t < NN; t += NTHREADS) sloc[t] = locb[t];
    if (tid < 256) hist[tid] = 0;
    if (tid == 0) s_m = 0;
    __syncthreads();

    const float2 my = sloc[i];

    // Pass 1: d^2 bits (monotone in distance; sqrt deferred to candidates).
    // Self-loop / pad slots get +inf bits. Level-1 histogram on the 8-bit
    // exponent with match_any warp aggregation (bins are exponent-concentrated).
    for (int t = tid; t < 1024; t += NTHREADS) {       // exactly 4 full iters
        unsigned int v = 0x7F800000u;                  // +inf
        if (t < NN && t != i) {
            float dx = my.x - sloc[t].x;
            float dy = my.y - sloc[t].y;
            // Match jax f32 arithmetic exactly; forbid fma contraction.
            float d2 = __fadd_rn(__fadd_rn(__fmul_rn(dx, dx), __fmul_rn(dy, dy)),
                                 1e-12f);
            v = __float_as_uint(d2);                   // d2 > 0 => bits monotone
        }
        db2[t] = v;
        unsigned int bin  = v >> 23;
        unsigned int mask = __match_any_sync(0xFFFFFFFFu, bin);
        if (lane == __ffs(mask) - 1) atomicAdd(&hist[bin], __popc(mask));
    }
    __syncthreads();

    // Level-1 cutoff: exponent bin holding rank KK (one bin per thread).
    {
        unsigned int s = hist[tid];
        unsigned int e = block_excl_scan_256(s, wsum, tid);
        if (e < KK && KK <= e + s) { s_c1 = (unsigned)tid; s_less1 = e; }
    }
    __syncthreads();
    const unsigned int c1    = s_c1;
    const unsigned int less1 = s_less1;
    hist[tid] = 0;
    __syncthreads();

    // Level-2 histogram: next 8 mantissa bits within the cutoff exponent bin.
    for (int t = tid; t < 1024; t += NTHREADS) {
        unsigned int v = db2[t];
        if ((v >> 23) == c1) atomicAdd(&hist[(v >> 15) & 0xFFu], 1u);
    }
    __syncthreads();
    {
        const unsigned int K2 = KK - less1;            // >= 1
        unsigned int s = hist[tid];
        unsigned int e = block_excl_scan_256(s, wsum, tid);
        if (e < K2 && K2 <= e + s) s_P = (c1 << 8) | (unsigned)tid;
    }
    __syncthreads();
    // Include one extra sub-bin: guarantees every item whose ROUNDED distance
    // could tie the rank-50 boundary (sqrt rounding collisions) is captured,
    // since items beyond P+1 differ by >= ~2^-10 relative in d^2 -> strictly
    // larger rounded d than any true top-50 member.
    const unsigned int Pp1 = s_P + 1;

    // Compaction (ballot-aggregated counter). sqrt only for candidates; the
    // candidate key is the exact jax ordering key: (bits(d) << 10) | idx.
    for (int t = tid; t < 1024; t += NTHREADS) {
        unsigned int v   = db2[t];
        bool         sel = ((v >> 15) <= Pp1);
        unsigned int msk = __ballot_sync(0xFFFFFFFFu, sel);
        if (msk) {
            unsigned int base = 0;
            int leader = __ffs(msk) - 1;
            if (lane == leader) base = atomicAdd(&s_m, __popc(msk));
            base = __shfl_sync(0xFFFFFFFFu, base, leader);
            if (sel) {
                unsigned int pos = base + __popc(msk & ((1u << lane) - 1u));
                if (pos < CAND_CAP) {
                    float d = __fsqrt_rn(__uint_as_float(v));  // IEEE rn sqrt
                    cand[pos] = ((unsigned long long)__float_as_uint(d) << 10)
                                | (unsigned)t;
                }
            }
        }
    }
    __syncthreads();

    // Rank-select: keys are unique (idx in low bits), so ranks are a
    // permutation. Broadcast LDS loop — no barriers, no sort.
    const unsigned int m = min(s_m, (unsigned)CAND_CAP);
    if (tid < (int)m) {
        const unsigned long long mykey = cand[tid];
        unsigned int r = 0;
        for (unsigned int t = 0; t < m; ++t)
            r += (cand[t] < mykey);
        if (r < KK) {
            float d  = __uint_as_float((unsigned int)(mykey >> 10));
            int   nb = (int)(mykey & 1023u);
            sdist[r] = d;
            const long long e = (long long)row * KK + r;
            float* src = out + X_ELEMS;
            float* dst = src + E_ELEMS;
            src[e] = (float)row;
            dst[e] = (float)(b * NN + nb);
        }
    }
    __syncthreads();

    // edge_emb[e, :] = dist_e * W + bias, STG.128: one warp per row-slice,
    // 8 rows in flight across the block.
    const float4* W4 = reinterpret_cast<const float4*>(W);
    const float4* B4 = reinterpret_cast<const float4*>(bias);
    const float4  w4 = __ldg(W4 + lane);
    const float4  b4 = __ldg(B4 + lane);
    float4* emb = reinterpret_cast<float4*>(out + X_ELEMS + 2LL * E_ELEMS);
    const int g = tid >> 5;                            // warp id 0..7
    const long long base = (long long)row * KK;
    for (int s = g; s < KK; s += 8) {
        const float dd = sdist[s];
        float4 v;
        v.x = fmaf(dd, w4.x, b4.x);
        v.y = fmaf(dd, w4.y, b4.y);
        v.z = fmaf(dd, w4.z, b4.z);
        v.w = fmaf(dd, w4.w, b4.w);
        emb[(base + s) * 32 + lane] = v;
    }
}

extern "C" void kernel_launch(void* const* d_in, const int* in_sizes, int n_in,
                              void* d_out, int out_size)
{
    const float* locs = (const float*)d_in[0];   // [16, 1000, 2]
    const float* xin  = (const float*)d_in[1];   // [16, 1000, 128]
    const float* W    = (const float*)d_in[2];   // [1, 128]
    const float* bias = (const float*)d_in[3];   // [128]
    float* out = (float*)d_out;

    tsp_topk_kernel<<<BB * NN, NTHREADS, 0, 0>>>(locs, xin, W, bias, out);
}

// round 7
// speedup vs baseline: 5.6893x; 1.0159x over previous
#include <cuda_runtime.h>
#include <cstdint>

// Problem constants (fixed by reference setup_inputs)
#define BB   16
#define NN   1000
#define KK   50
#define DD   128
#define NTHREADS 256
#define CAND_CAP 256

// Output layout (float32, concatenation of reference outputs):
//   [0,        2048000)   x = init_embeddings
//   [2048000,  2848000)   edge_index row 0 (src)
//   [2848000,  3648000)   edge_index row 1 (dst)
//   [3648000, 106048000)  edge_emb [B*n*k, D]
#define X_ELEMS   (BB * NN * DD)
#define E_ELEMS   (BB * NN * KK)

__global__ __launch_bounds__(NTHREADS, 6)
void tsp_topk_kernel(const float* __restrict__ locs,   // [B, N, 2]
                     const float* __restrict__ xin,    // [B, N, 128]
                     const float* __restrict__ W,      // [128]
                     const float* __restrict__ bias,   // [128]
                     float* __restrict__ out)
{
    __shared__ __align__(16) float2 sloc[NN];          // 8000 B
    __shared__ unsigned int hist1[256];                // 1 KB
    __shared__ unsigned int hist2[256];                // 1 KB (pre-cleared)
    __shared__ unsigned long long cand[CAND_CAP];      // 2 KB
    __shared__ unsigned int s_c1, s_less1, s_P, s_m;
    __shared__ float sdist[KK];

    const int row  = blockIdx.x;         // global node index b*NN + i
    const int b    = row / NN;
    const int i    = row - b * NN;
    const int tid  = threadIdx.x;
    const int lane = tid & 31;
    const int wid  = tid >> 5;

    // Stage this batch's locations (float4 = 2 points per load); clear both
    // histograms up front (hist2 pre-cleared saves a barrier pair later).
    {
        const float4* l4 = reinterpret_cast<const float4*>(locs + (size_t)b * NN * 2);
        float4*       s4 = reinterpret_cast<float4*>(sloc);
        for (int t = tid; t < NN / 2; t += NTHREADS) s4[t] = l4[t];
    }
    hist1[tid] = 0;
    hist2[tid] = 0;
    if (tid == 0) s_m = 0;
    __syncthreads();

    const float2 my = sloc[i];

    // Pass 1: d^2 bits for 4 contiguous points, REGISTER-resident (no db2
    // array). d^2 > 0 so float bits are order-monotone; sqrt deferred to
    // candidates. Level-1 histogram on the 8-bit exponent with match_any
    // warp aggregation (bins are exponent-concentrated).
    unsigned int r[4];
    {
        const float4* s4  = reinterpret_cast<const float4*>(sloc);
        const float4  p01 = s4[tid * 2];
        const float4  p23 = s4[tid * 2 + 1];
        const float px[4] = {p01.x, p01.z, p23.x, p23.z};
        const float py[4] = {p01.y, p01.w, p23.y, p23.w};
        #pragma unroll
        for (int j = 0; j < 4; ++j) {
            const int t = 4 * tid + j;
            unsigned int v = 0x7F800000u;              // +inf: self-loop / pad
            if (t < NN && t != i) {
                float dx = my.x - px[j];
                float dy = my.y - py[j];
                // Match jax f32 arithmetic exactly; forbid fma contraction.
                float d2 = __fadd_rn(__fadd_rn(__fmul_rn(dx, dx),
                                               __fmul_rn(dy, dy)), 1e-12f);
                v = __float_as_uint(d2);
            }
            r[j] = v;
            unsigned int bin  = v >> 23;
            unsigned int mask = __match_any_sync(0xFFFFFFFFu, bin);
            if (lane == __ffs(mask) - 1) atomicAdd(&hist1[bin], __popc(mask));
        }
    }
    __syncthreads();

    // Level-1 cutoff on warp 0 only: exponent bin holding rank KK.
    if (wid == 0) {
        unsigned int h[8], s = 0;
        #pragma unroll
        for (int j = 0; j < 8; ++j) { h[j] = hist1[lane * 8 + j]; s += h[j]; }
        unsigned int incl = s;
        #pragma unroll
        for (int o = 1; o < 32; o <<= 1) {
            unsigned int x = __shfl_up_sync(0xFFFFFFFFu, incl, o);
            if (lane >= o) incl += x;
        }
        const unsigned int e = incl - s;
        if (e < KK && KK <= incl) {
            unsigned int cum = e;
            #pragma unroll
            for (int j = 0; j < 8; ++j) {
                if (KK <= cum + h[j]) { s_c1 = lane * 8 + j; s_less1 = cum; break; }
                cum += h[j];
            }
        }
    }
    __syncthreads();
    const unsigned int c1 = s_c1;

    // Level-2 histogram from registers: next 8 mantissa bits within the
    // cutoff exponent bin (hist2 already cleared).
    #pragma unroll
    for (int j = 0; j < 4; ++j) {
        unsigned int v = r[j];
        if ((v >> 23) == c1) atomicAdd(&hist2[(v >> 15) & 0xFFu], 1u);
    }
    __syncthreads();

    // Level-2 cutoff on warp 0 only.
    if (wid == 0) {
        const unsigned int K2 = KK - s_less1;          // >= 1
        unsigned int h[8], s = 0;
        #pragma unroll
        for (int j = 0; j < 8; ++j) { h[j] = hist2[lane * 8 + j]; s += h[j]; }
        unsigned int incl = s;
        #pragma unroll
        for (int o = 1; o < 32; o <<= 1) {
            unsigned int x = __shfl_up_sync(0xFFFFFFFFu, incl, o);
            if (lane >= o) incl += x;
        }
        const unsigned int e = incl - s;
        if (e < K2 && K2 <= incl) {
            unsigned int cum = e;
            #pragma unroll
            for (int j = 0; j < 8; ++j) {
                if (K2 <= cum + h[j]) { s_P = (c1 << 8) | (lane * 8 + j); break; }
                cum += h[j];
            }
        }
    }
    __syncthreads();
    // One extra sub-bin: captures every item whose ROUNDED distance could tie
    // the rank-50 boundary (sqrt rounding collisions); anything beyond P+1
    // differs by >= ~2^-10 relative in d^2 -> strictly larger rounded d.
    const unsigned int Pp1 = s_P + 1;

    // Compaction from registers (ballot-aggregated counter). sqrt only for
    // candidates; key is the exact jax ordering key: (bits(d) << 10) | idx,
    // so equal distances tie-break to the lower index like lax.top_k.
    #pragma unroll
    for (int j = 0; j < 4; ++j) {
        unsigned int v   = r[j];
        bool         sel = ((v >> 15) <= Pp1);
        unsigned int msk = __ballot_sync(0xFFFFFFFFu, sel);
        if (msk) {
            unsigned int base = 0;
            int leader = __ffs(msk) - 1;
            if (lane == leader) base = atomicAdd(&s_m, __popc(msk));
            base = __shfl_sync(0xFFFFFFFFu, base, leader);
            if (sel) {
                unsigned int pos = base + __popc(msk & ((1u << lane) - 1u));
                if (pos < CAND_CAP) {
                    float d = __fsqrt_rn(__uint_as_float(v));  // IEEE rn sqrt
                    cand[pos] = ((unsigned long long)__float_as_uint(d) << 10)
                                | (unsigned)(4 * tid + j);
                }
            }
        }
    }
    __syncthreads();

    // Rank-select: keys are unique (idx in low bits) -> ranks are a
    // permutation. Broadcast LDS loop on ~2 warps, zero barriers, no sort.
    const unsigned int m = min(s_m, (unsigned)CAND_CAP);
    if (tid < (int)m) {
        const unsigned long long mykey = cand[tid];
        unsigned int rk = 0;
        for (unsigned int t = 0; t < m; ++t)
            rk += (cand[t] < mykey);
        if (rk < KK) {
            float d  = __uint_as_float((unsigned int)(mykey >> 10));
            int   nb = (int)(mykey & 1023u);
            sdist[rk] = d;
            const long long e = (long long)row * KK + rk;
            float* src = out + X_ELEMS;
            float* dst = src + E_ELEMS;
            src[e] = (float)row;
            dst[e] = (float)(b * NN + nb);
        }
    }
    __syncthreads();

    // x output (copy of init_embeddings): warp 7 handles this row's 512B;
    // LDG latency hides under the other warps' store stream below.
    if (wid == 7) {
        const float4* xr = reinterpret_cast<const float4*>(xin) + (size_t)row * 32;
        float4*       xo = reinterpret_cast<float4*>(out) + (size_t)row * 32;
        xo[lane] = xr[lane];
    }

    // edge_emb[e, :] = dist_e * W + bias. One warp per row-slice, packed
    // f32x2 FMA (2 FFMA2 instead of 4 FFMA) + streaming STG.128.
    const float4 w4 = __ldg(reinterpret_cast<const float4*>(W) + lane);
    const float4 b4 = __ldg(reinterpret_cast<const float4*>(bias) + lane);
    unsigned long long wlo, whi, blo, bhi;
    asm("mov.b64 %0, {%1, %2};" : "=l"(wlo) : "f"(w4.x), "f"(w4.y));
    asm("mov.b64 %0, {%1, %2};" : "=l"(whi) : "f"(w4.z), "f"(w4.w));
    asm("mov.b64 %0, {%1, %2};" : "=l"(blo) : "f"(b4.x), "f"(b4.y));
    asm("mov.b64 %0, {%1, %2};" : "=l"(bhi) : "f"(b4.z), "f"(b4.w));
    float4* emb = reinterpret_cast<float4*>(out + X_ELEMS + 2LL * E_ELEMS);
    const long long base = (long long)row * KK;
    #pragma unroll
    for (int s = wid; s < KK; s += 8) {
        const float dd = sdist[s];
        unsigned long long dd2, o01, o23;
        asm("mov.b64 %0, {%1, %1};" : "=l"(dd2) : "f"(dd));
        asm("fma.rn.f32x2 %0, %1, %2, %3;" : "=l"(o01) : "l"(dd2), "l"(wlo), "l"(blo));
        asm("fma.rn.f32x2 %0, %1, %2, %3;" : "=l"(o23) : "l"(dd2), "l"(whi), "l"(bhi));
        float4 v;
        asm("mov.b64 {%0, %1}, %2;" : "=f"(v.x), "=f"(v.y) : "l"(o01));
        asm("mov.b64 {%0, %1}, %2;" : "=f"(v.z), "=f"(v.w) : "l"(o23));
        __stcs(emb + (base + s) * 32 + lane, v);
    }
}

extern "C" void kernel_launch(void* const* d_in, const int* in_sizes, int n_in,
                              void* d_out, int out_size)
{
    const float* locs = (const float*)d_in[0];   // [16, 1000, 2]
    const float* xin  = (const float*)d_in[1];   // [16, 1000, 128]
    const float* W    = (const float*)d_in[2];   // [1, 128]
    const float* bias = (const float*)d_in[3];   // [128]
    float* out = (float*)d_out;

    tsp_topk_kernel<<<BB * NN, NTHREADS, 0, 0>>>(locs, xin, W, bias, out);
}

// round 8
// speedup vs baseline: 7.1466x; 1.2561x over previous
#include <cuda_runtime.h>
#include <cstdint>

// Problem constants (fixed by reference setup_inputs)
#define BB   16
#define NN   1000
#define KK   50
#define DD   128
#define NTHREADS 256
#define WPB  8            // warps (= nodes) per block
#define CAND_CAP 96       // per-warp candidate buffer (m typically ~55)

// Output layout (float32, concatenation of reference outputs):
//   [0,        2048000)   x = init_embeddings
//   [2048000,  2848000)   edge_index row 0 (src)
//   [2848000,  3648000)   edge_index row 1 (dst)
//   [3648000, 106048000)  edge_emb [B*n*k, D]
#define X_ELEMS   (BB * NN * DD)
#define E_ELEMS   (BB * NN * KK)

#define FULLMASK 0xFFFFFFFFu

__global__ __launch_bounds__(NTHREADS)
void tsp_topk_kernel(const float* __restrict__ locs,   // [B, N, 2]
                     const float* __restrict__ xin,    // [B, N, 128]
                     const float* __restrict__ W,      // [128]
                     const float* __restrict__ bias,   // [128]
                     float* __restrict__ out)
{
    __shared__ __align__(16) float2 sloc[NN];              // 8000 B
    __shared__ unsigned int hist[WPB][256];                // 8 KB (per-warp)
    __shared__ unsigned long long cand[WPB][CAND_CAP];     // 6 KB (per-warp)
    __shared__ float        sdist[WPB][KK];                // 1.6 KB
    __shared__ unsigned int snbr [WPB][KK];                // 1.6 KB

    const int tid  = threadIdx.x;
    const int lane = tid & 31;
    const int wid  = tid >> 5;
    const int b    = blockIdx.x / (NN / WPB);   // 125 blocks per batch, exact
    const int node = blockIdx.x * WPB + wid;    // global node index b*NN + i
    const int i    = node - b * NN;

    // Stage this batch's locations (float4 = 2 points/load). Only block-wide
    // barrier in the kernel. Per-warp hist cleared alongside.
    {
        const float4* l4 = reinterpret_cast<const float4*>(locs + (size_t)b * NN * 2);
        float4*       s4 = reinterpret_cast<float4*>(sloc);
        for (int t = tid; t < NN / 2; t += NTHREADS) s4[t] = l4[t];
    }
    #pragma unroll
    for (int j = 0; j < 8; ++j) hist[wid][lane * 8 + j] = 0;
    __syncthreads();

    const float2 my = sloc[i];

    // d^2 bits for point t (monotone key: d^2 > 0 so float bits order == value
    // order). Self-loop / pad -> +inf. Matches jax f32 arithmetic exactly.
    #define DIST2BITS(t, v)                                                   \
        do {                                                                  \
            (v) = 0x7F800000u;                                                \
            if ((t) < NN && (t) != i) {                                       \
                float dx = my.x - sloc[(t)].x;                                \
                float dy = my.y - sloc[(t)].y;                                \
                float d2 = __fadd_rn(__fadd_rn(__fmul_rn(dx, dx),             \
                                               __fmul_rn(dy, dy)), 1e-12f);   \
                (v) = __float_as_uint(d2);                                    \
            }                                                                 \
        } while (0)

    // ---- Pass A: level-1 histogram on the 8-bit exponent (per-warp hist,
    // match_any aggregation since bins are exponent-concentrated). ----
    for (int j = 0; j < 32; ++j) {
        const int t = lane + 32 * j;
        unsigned int v; DIST2BITS(t, v);
        unsigned int bin  = v >> 23;
        unsigned int mask = __match_any_sync(FULLMASK, bin);
        if (lane == __ffs(mask) - 1) atomicAdd(&hist[wid][bin], __popc(mask));
    }
    __syncwarp();

    // ---- Level-1 cutoff (all lanes of this warp; no barrier). ----
    unsigned int c1, less1;
    {
        unsigned int h[8], s = 0;
        #pragma unroll
        for (int j = 0; j < 8; ++j) { h[j] = hist[wid][lane * 8 + j]; s += h[j]; }
        unsigned int incl = s;
        #pragma unroll
        for (int o = 1; o < 32; o <<= 1) {
            unsigned int x = __shfl_up_sync(FULLMASK, incl, o);
            if (lane >= o) incl += x;
        }
        const unsigned int e   = incl - s;
        const bool         has = (e < KK && KK <= incl);   // exactly one lane
        unsigned int cc = 0, ll = 0;
        if (has) {
            unsigned int cum = e;
            #pragma unroll
            for (int j = 0; j < 8; ++j) {
                if (KK <= cum + h[j]) { cc = lane * 8 + j; ll = cum; break; }
                cum += h[j];
            }
        }
        const int srcl = __ffs(__ballot_sync(FULLMASK, has)) - 1;
        c1    = __shfl_sync(FULLMASK, cc, srcl);
        less1 = __shfl_sync(FULLMASK, ll, srcl);
    }

    // ---- Pass B: level-2 histogram (next 8 mantissa bits) within bin c1. ----
    #pragma unroll
    for (int j = 0; j < 8; ++j) hist[wid][lane * 8 + j] = 0;
    __syncwarp();
    for (int j = 0; j < 32; ++j) {
        const int t = lane + 32 * j;
        unsigned int v; DIST2BITS(t, v);
        if ((v >> 23) == c1) atomicAdd(&hist[wid][(v >> 15) & 0xFFu], 1u);
    }
    __syncwarp();

    // ---- Level-2 cutoff -> 16-bit prefix P; +1 sub-bin guard band captures
    // every sqrt-rounding tie at the rank-50 boundary. ----
    unsigned int Pp1;
    {
        const unsigned int K2 = KK - less1;                // >= 1
        unsigned int h[8], s = 0;
        #pragma unroll
        for (int j = 0; j < 8; ++j) { h[j] = hist[wid][lane * 8 + j]; s += h[j]; }
        unsigned int incl = s;
        #pragma unroll
        for (int o = 1; o < 32; o <<= 1) {
            unsigned int x = __shfl_up_sync(FULLMASK, incl, o);
            if (lane >= o) incl += x;
        }
        const unsigned int e   = incl - s;
        const bool         has = (e < K2 && K2 <= incl);
        unsigned int pp = 0;
        if (has) {
            unsigned int cum = e;
            #pragma unroll
            for (int j = 0; j < 8; ++j) {
                if (K2 <= cum + h[j]) { pp = (c1 << 8) | (lane * 8 + j); break; }
                cum += h[j];
            }
        }
        const int srcl = __ffs(__ballot_sync(FULLMASK, has)) - 1;
        Pp1 = __shfl_sync(FULLMASK, pp, srcl) + 1;
    }

    // ---- Pass C: compaction with register running-prefix (no atomics).
    // sqrt only on candidates; key = exact jax ordering key (bits(d)<<10)|idx,
    // so equal distances tie-break to the lower index like lax.top_k. ----
    unsigned int cnt = 0;
    for (int j = 0; j < 32; ++j) {
        const int t = lane + 32 * j;
        unsigned int v; DIST2BITS(t, v);
        const bool         sel = ((v >> 15) <= Pp1);
        const unsigned int msk = __ballot_sync(FULLMASK, sel);
        if (sel) {
            unsigned int pos = cnt + __popc(msk & ((1u << lane) - 1u));
            if (pos < CAND_CAP) {
                float d = __fsqrt_rn(__uint_as_float(v));  // IEEE rn sqrt
                cand[wid][pos] =
                    ((unsigned long long)__float_as_uint(d) << 10) | (unsigned)t;
            }
        }
        cnt += __popc(msk);
    }
    const unsigned int m = min(cnt, (unsigned)CAND_CAP);
    __syncwarp();

    // Issue the x-row load now; its latency hides under the rank loop.
    const float4 xv =
        reinterpret_cast<const float4*>(xin)[(size_t)node * 32 + lane];

    // ---- Rank-select: keys unique (idx in low bits) -> ranks are a
    // permutation; broadcast-LDS counting loop, no sort, no barriers. ----
    for (unsigned int q = lane; q < m; q += 32) {
        const unsigned long long mykey = cand[wid][q];
        unsigned int rk = 0;
        for (unsigned int t = 0; t < m; ++t)
            rk += (cand[wid][t] < mykey);
        if (rk < KK) {
            sdist[wid][rk] = __uint_as_float((unsigned int)(mykey >> 10));
            snbr [wid][rk] = (unsigned int)(mykey & 1023u);
        }
    }
    __syncwarp();

    // ---- edge_index (coalesced, as float) + x output. ----
    {
        float* srcp = out + X_ELEMS;
        float* dstp = srcp + E_ELEMS;
        const long long e0 = (long long)node * KK;
        #pragma unroll
        for (int s = lane; s < KK; s += 32) {
            srcp[e0 + s] = (float)node;
            dstp[e0 + s] = (float)(b * NN + (int)snbr[wid][s]);
        }
        reinterpret_cast<float4*>(out)[(size_t)node * 32 + lane] = xv;
    }

    // ---- edge_emb[e, :] = dist_e * W + bias; 50 streaming STG.128 rows. ----
    const float4 w4 = __ldg(reinterpret_cast<const float4*>(W) + lane);
    const float4 b4 = __ldg(reinterpret_cast<const float4*>(bias) + lane);
    float4* emb = reinterpret_cast<float4*>(out + X_ELEMS + 2LL * E_ELEMS);
    const long long base = (long long)node * KK;
    #pragma unroll 5
    for (int s = 0; s < KK; ++s) {
        const float dd = sdist[wid][s];
        float4 v;
        v.x = fmaf(dd, w4.x, b4.x);
        v.y = fmaf(dd, w4.y, b4.y);
        v.z = fmaf(dd, w4.z, b4.z);
        v.w = fmaf(dd, w4.w, b4.w);
        __stcs(emb + (base + s) * 32 + lane, v);
    }
    #undef DIST2BITS
}

extern "C" void kernel_launch(void* const* d_in, const int* in_sizes, int n_in,
                              void* d_out, int out_size)
{
    const float* locs = (const float*)d_in[0];   // [16, 1000, 2]
    const float* xin  = (const float*)d_in[1];   // [16, 1000, 128]
    const float* W    = (const float*)d_in[2];   // [1, 128]
    const float* bias = (const float*)d_in[3];   // [128]
    float* out = (float*)d_out;

    tsp_topk_kernel<<<(BB * NN) / WPB, NTHREADS, 0, 0>>>(locs, xin, W, bias, out);
}

// round 9
// speedup vs baseline: 7.4294x; 1.0396x over previous
#include <cuda_runtime.h>
#include <cstdint>

// Problem constants (fixed by reference setup_inputs)
#define BB   16
#define NN   1000
#define KK   50
#define DD   128
#define NTHREADS 256
#define WPB  8            // warps (= nodes) per block
#define CAND_CAP 96       // per-warp candidate buffer (m typically ~55)

// Output layout (float32, concatenation of reference outputs):
//   [0,        2048000)   x = init_embeddings
//   [2048000,  2848000)   edge_index row 0 (src)
//   [2848000,  3648000)   edge_index row 1 (dst)
//   [3648000, 106048000)  edge_emb [B*n*k, D]
#define X_ELEMS   (BB * NN * DD)
#define E_ELEMS   (BB * NN * KK)

#define FULLMASK 0xFFFFFFFFu

__global__ __launch_bounds__(NTHREADS, 7)
void tsp_topk_kernel(const float* __restrict__ locs,   // [B, N, 2]
                     const float* __restrict__ xin,    // [B, N, 128]
                     const float* __restrict__ W,      // [128]
                     const float* __restrict__ bias,   // [128]
                     float* __restrict__ out)
{
    __shared__ __align__(16) float2 sloc[1024];            // 8192 B (24 pad slots)
    __shared__ unsigned int hist[WPB][256];                // 8 KB (per-warp)
    __shared__ unsigned long long cand[WPB][CAND_CAP];     // 6 KB (per-warp)
    __shared__ float        sdist[WPB][KK];                // 1.6 KB
    __shared__ unsigned int snbr [WPB][KK];                // 1.6 KB

    const int tid  = threadIdx.x;
    const int lane = tid & 31;
    const int wid  = tid >> 5;
    const int b    = blockIdx.x / (NN / WPB);   // 125 blocks per batch, exact
    const int node = blockIdx.x * WPB + wid;    // global node index b*NN + i
    const int i    = node - b * NN;

    // x output first: keeps DRAM busy during the selection phase.
    reinterpret_cast<float4*>(out)[(size_t)node * 32 + lane] =
        reinterpret_cast<const float4*>(xin)[(size_t)node * 32 + lane];

    // Stage this batch's locations (float4 = 2 points/load). The only
    // block-wide barrier in the kernel. Per-warp hist cleared alongside.
    {
        const float4* l4 = reinterpret_cast<const float4*>(locs + (size_t)b * NN * 2);
        float4*       s4 = reinterpret_cast<float4*>(sloc);
        for (int t = tid; t < NN / 2; t += NTHREADS) s4[t] = l4[t];
    }
    #pragma unroll
    for (int j = 0; j < 8; ++j) hist[wid][lane * 8 + j] = 0;
    __syncthreads();

    const float2 my = sloc[i];
    const float4* s4loc = reinterpret_cast<const float4*>(sloc);

    // d^2 bits for point t with coords (px,py): monotone key (d^2 > 0 so
    // float bits order == value order). Self-loop / pad -> +inf. Matches jax
    // f32 arithmetic exactly (no fma contraction).
    #define D2BITS(t, px, py, v)                                              \
        do {                                                                  \
            (v) = 0x7F800000u;                                                \
            if ((t) < NN && (t) != i) {                                       \
                float dx = my.x - (px);                                       \
                float dy = my.y - (py);                                       \
                float d2 = __fadd_rn(__fadd_rn(__fmul_rn(dx, dx),             \
                                               __fmul_rn(dy, dy)), 1e-12f);   \
                (v) = __float_as_uint(d2);                                    \
            }                                                                 \
        } while (0)

    // ---- Pass A: level-1 histogram on the 8-bit exponent. 2 points per
    // LDS.128; per-warp hist; match_any aggregation (bins are
    // exponent-concentrated). ----
    for (int j = 0; j < 16; ++j) {
        const int    q  = lane + 32 * j;
        const float4 p  = s4loc[q];
        const int    t0 = 2 * q;
        unsigned int v0, v1;
        D2BITS(t0,     p.x, p.y, v0);
        D2BITS(t0 + 1, p.z, p.w, v1);
        unsigned int m0 = __match_any_sync(FULLMASK, v0 >> 23);
        if (lane == __ffs(m0) - 1) atomicAdd(&hist[wid][v0 >> 23], __popc(m0));
        unsigned int m1 = __match_any_sync(FULLMASK, v1 >> 23);
        if (lane == __ffs(m1) - 1) atomicAdd(&hist[wid][v1 >> 23], __popc(m1));
    }
    __syncwarp();

    // ---- Level-1 cutoff (all lanes of this warp; no barrier). ----
    unsigned int c1, less1;
    {
        unsigned int h[8], s = 0;
        #pragma unroll
        for (int j = 0; j < 8; ++j) { h[j] = hist[wid][lane * 8 + j]; s += h[j]; }
        unsigned int incl = s;
        #pragma unroll
        for (int o = 1; o < 32; o <<= 1) {
            unsigned int x = __shfl_up_sync(FULLMASK, incl, o);
            if (lane >= o) incl += x;
        }
        const unsigned int e   = incl - s;
        const bool         has = (e < KK && KK <= incl);   // exactly one lane
        unsigned int cc = 0, ll = 0;
        if (has) {
            unsigned int cum = e;
            #pragma unroll
            for (int j = 0; j < 8; ++j) {
                if (KK <= cum + h[j]) { cc = lane * 8 + j; ll = cum; break; }
                cum += h[j];
            }
        }
        const int srcl = __ffs(__ballot_sync(FULLMASK, has)) - 1;
        c1    = __shfl_sync(FULLMASK, cc, srcl);
        less1 = __shfl_sync(FULLMASK, ll, srcl);
    }

    // ---- Pass B: level-2 histogram (next 8 mantissa bits) within bin c1. ----
    #pragma unroll
    for (int j = 0; j < 8; ++j) hist[wid][lane * 8 + j] = 0;
    __syncwarp();
    for (int j = 0; j < 16; ++j) {
        const int    q  = lane + 32 * j;
        const float4 p  = s4loc[q];
        const int    t0 = 2 * q;
        unsigned int v0, v1;
        D2BITS(t0,     p.x, p.y, v0);
        D2BITS(t0 + 1, p.z, p.w, v1);
        if ((v0 >> 23) == c1) atomicAdd(&hist[wid][(v0 >> 15) & 0xFFu], 1u);
        if ((v1 >> 23) == c1) atomicAdd(&hist[wid][(v1 >> 15) & 0xFFu], 1u);
    }
    __syncwarp();

    // ---- Level-2 cutoff -> 16-bit prefix P; +1 sub-bin guard band captures
    // every sqrt-rounding tie at the rank-50 boundary. ----
    unsigned int Pp1;
    {
        const unsigned int K2 = KK - less1;                // >= 1
        unsigned int h[8], s = 0;
        #pragma unroll
        for (int j = 0; j < 8; ++j) { h[j] = hist[wid][lane * 8 + j]; s += h[j]; }
        unsigned int incl = s;
        #pragma unroll
        for (int o = 1; o < 32; o <<= 1) {
            unsigned int x = __shfl_up_sync(FULLMASK, incl, o);
            if (lane >= o) incl += x;
        }
        const unsigned int e   = incl - s;
        const bool         has = (e < K2 && K2 <= incl);
        unsigned int pp = 0;
        if (has) {
            unsigned int cum = e;
            #pragma unroll
            for (int j = 0; j < 8; ++j) {
                if (K2 <= cum + h[j]) { pp = (c1 << 8) | (lane * 8 + j); break; }
                cum += h[j];
            }
        }
        const int srcl = __ffs(__ballot_sync(FULLMASK, has)) - 1;
        Pp1 = __shfl_sync(FULLMASK, pp, srcl) + 1;
    }

    // ---- Pass C: compaction with register running-prefix (no atomics).
    // sqrt only on candidates; key = exact jax ordering key (bits(d)<<10)|idx,
    // so equal distances tie-break to the lower index like lax.top_k.
    // Candidate buffer order is arbitrary — ranking below is by global key. ----
    unsigned int cnt = 0;
    for (int j = 0; j < 16; ++j) {
        const int    q  = lane + 32 * j;
        const float4 p  = s4loc[q];
        const int    t0 = 2 * q;
        unsigned int v0, v1;
        D2BITS(t0,     p.x, p.y, v0);
        D2BITS(t0 + 1, p.z, p.w, v1);

        bool         sel = ((v0 >> 15) <= Pp1);
        unsigned int msk = __ballot_sync(FULLMASK, sel);
        if (sel) {
            unsigned int pos = cnt + __popc(msk & ((1u << lane) - 1u));
            if (pos < CAND_CAP) {
                float d = __fsqrt_rn(__uint_as_float(v0));  // IEEE rn sqrt
                cand[wid][pos] =
                    ((unsigned long long)__float_as_uint(d) << 10) | (unsigned)t0;
            }
        }
        cnt += __popc(msk);

        sel = ((v1 >> 15) <= Pp1);
        msk = __ballot_sync(FULLMASK, sel);
        if (sel) {
            unsigned int pos = cnt + __popc(msk & ((1u << lane) - 1u));
            if (pos < CAND_CAP) {
                float d = __fsqrt_rn(__uint_as_float(v1));
                cand[wid][pos] =
                    ((unsigned long long)__float_as_uint(d) << 10)
                    | (unsigned)(t0 + 1);
            }
        }
        cnt += __popc(msk);
    }
    const unsigned int m = min(cnt, (unsigned)CAND_CAP);
    __syncwarp();

    // ---- Rank-select: keys unique (idx in low bits) -> ranks are a
    // permutation; broadcast-LDS counting loop, no sort, no barriers. ----
    for (unsigned int q = lane; q < m; q += 32) {
        const unsigned long long mykey = cand[wid][q];
        unsigned int rk = 0;
        for (unsigned int t = 0; t < m; ++t)
            rk += (cand[wid][t] < mykey);
        if (rk < KK) {
            sdist[wid][rk] = __uint_as_float((unsigned int)(mykey >> 10));
            snbr [wid][rk] = (unsigned int)(mykey & 1023u);
        }
    }
    __syncwarp();

    // ---- edge_index (coalesced, as float). ----
    {
        float* srcp = out + X_ELEMS;
        float* dstp = srcp + E_ELEMS;
        const long long e0 = (long long)node * KK;
        #pragma unroll
        for (int s = lane; s < KK; s += 32) {
            srcp[e0 + s] = (float)node;
            dstp[e0 + s] = (float)(b * NN + (int)snbr[wid][s]);
        }
    }

    // ---- edge_emb[e, :] = dist_e * W + bias; 50 streaming STG.128 rows. ----
    const float4 w4 = __ldg(reinterpret_cast<const float4*>(W) + lane);
    const float4 b4 = __ldg(reinterpret_cast<const float4*>(bias) + lane);
    float4* emb = reinterpret_cast<float4*>(out + X_ELEMS + 2LL * E_ELEMS);
    const long long base = (long long)node * KK;
    #pragma unroll 5
    for (int s = 0; s < KK; ++s) {
        const float dd = sdist[wid][s];
        float4 v;
        v.x = fmaf(dd, w4.x, b4.x);
        v.y = fmaf(dd, w4.y, b4.y);
        v.z = fmaf(dd, w4.z, b4.z);
        v.w = fmaf(dd, w4.w, b4.w);
        __stcs(emb + (base + s) * 32 + lane, v);
    }
    #undef D2BITS
}

extern "C" void kernel_launch(void* const* d_in, const int* in_sizes, int n_in,
                              void* d_out, int out_size)
{
    const float* locs = (const float*)d_in[0];   // [16, 1000, 2]
    const float* xin  = (const float*)d_in[1];   // [16, 1000, 128]
    const float* W    = (const float*)d_in[2];   // [1, 128]
    const float* bias = (const float*)d_in[3];   // [128]
    float* out = (float*)d_out;

    tsp_topk_kernel<<<(BB * NN) / WPB, NTHREADS, 0, 0>>>(locs, xin, W, bias, out);
}

// round 10
// speedup vs baseline: 7.6066x; 1.0239x over previous
#include <cuda_runtime.h>
#include <cstdint>

// Problem constants (fixed by reference setup_inputs)
#define BB   16
#define NN   1000
#define KK   50
#define DD   128
#define NTHREADS 256
#define WPB  8            // warps (= nodes) per block
#define CAND_CAP 224      // per-warp candidate buffer (mc typically ~100)

// Output layout (float32, concatenation of reference outputs):
//   [0,        2048000)   x = init_embeddings
//   [2048000,  2848000)   edge_index row 0 (src)
//   [2848000,  3648000)   edge_index row 1 (dst)
//   [3648000, 106048000)  edge_emb [B*n*k, D]
#define X_ELEMS   (BB * NN * DD)
#define E_ELEMS   (BB * NN * KK)

#define FULLMASK 0xFFFFFFFFu

__global__ __launch_bounds__(NTHREADS, 6)
void tsp_topk_kernel(const float* __restrict__ locs,   // [B, N, 2]
                     const float* __restrict__ xin,    // [B, N, 128]
                     const float* __restrict__ W,      // [128]
                     const float* __restrict__ bias,   // [128]
                     float* __restrict__ out)
{
    __shared__ __align__(16) float2 sloc[1024];            // 8192 B
    __shared__ unsigned int hist[WPB][256];                // 8 KB (per-warp)
    __shared__ unsigned long long cand[WPB][CAND_CAP];     // 14 KB (per-warp)
    __shared__ float        sdist[WPB][KK];                // 1.6 KB
    __shared__ unsigned int snbr [WPB][KK];                // 1.6 KB

    const int tid  = threadIdx.x;
    const int lane = tid & 31;
    const int wid  = tid >> 5;
    const int b    = blockIdx.x / (NN / WPB);   // 125 blocks per batch, exact
    const int node = blockIdx.x * WPB + wid;    // global node index b*NN + i
    const int i    = node - b * NN;

    // x output first: keeps DRAM busy during the selection phase.
    reinterpret_cast<float4*>(out)[(size_t)node * 32 + lane] =
        reinterpret_cast<const float4*>(xin)[(size_t)node * 32 + lane];

    // Stage this batch's locations (float4 = 2 points/load). The only
    // block-wide barrier in the kernel. Per-warp hist cleared alongside.
    {
        const float4* l4 = reinterpret_cast<const float4*>(locs + (size_t)b * NN * 2);
        float4*       s4 = reinterpret_cast<float4*>(sloc);
        for (int t = tid; t < NN / 2; t += NTHREADS) s4[t] = l4[t];
    }
    #pragma unroll
    for (int j = 0; j < 8; ++j) hist[wid][lane * 8 + j] = 0;
    __syncthreads();

    const float2 my = sloc[i];
    const float4* s4loc = reinterpret_cast<const float4*>(sloc);

    // d^2 bits for point t with coords (px,py): monotone key (d^2 > 0 so
    // float bits order == value order). Self-loop / pad -> +inf. Matches jax
    // f32 arithmetic exactly (no fma contraction).
    #define D2BITS(t, px, py, v)                                              \
        do {                                                                  \
            (v) = 0x7F800000u;                                                \
            if ((t) < NN && (t) != i) {                                       \
                float dx = my.x - (px);                                       \
                float dy = my.y - (py);                                       \
                float d2 = __fadd_rn(__fadd_rn(__fmul_rn(dx, dx),             \
                                               __fmul_rn(dy, dy)), 1e-12f);   \
                (v) = __float_as_uint(d2);                                    \
            }                                                                 \
        } while (0)

    // ---- Pass A: level-1 histogram on the 8-bit exponent. Unroll 4 batches
    // LDS.128s for MLP; per-warp hist; match_any aggregation. ----
    #pragma unroll 4
    for (int j = 0; j < 16; ++j) {
        const int    q  = lane + 32 * j;
        const float4 p  = s4loc[q];
        const int    t0 = 2 * q;
        unsigned int v0, v1;
        D2BITS(t0,     p.x, p.y, v0);
        D2BITS(t0 + 1, p.z, p.w, v1);
        unsigned int m0 = __match_any_sync(FULLMASK, v0 >> 23);
        if (lane == __ffs(m0) - 1) atomicAdd(&hist[wid][v0 >> 23], __popc(m0));
        unsigned int m1 = __match_any_sync(FULLMASK, v1 >> 23);
        if (lane == __ffs(m1) - 1) atomicAdd(&hist[wid][v1 >> 23], __popc(m1));
    }
    __syncwarp();

    // ---- Level-1 cutoff (all lanes of this warp; no barrier). ----
    unsigned int c1, less1;
    {
        unsigned int h[8], s = 0;
        #pragma unroll
        for (int j = 0; j < 8; ++j) { h[j] = hist[wid][lane * 8 + j]; s += h[j]; }
        unsigned int incl = s;
        #pragma unroll
        for (int o = 1; o < 32; o <<= 1) {
            unsigned int x = __shfl_up_sync(FULLMASK, incl, o);
            if (lane >= o) incl += x;
        }
        const unsigned int e   = incl - s;
        const bool         has = (e < KK && KK <= incl);   // exactly one lane
        unsigned int cc = 0, ll = 0;
        if (has) {
            unsigned int cum = e;
            #pragma unroll
            for (int j = 0; j < 8; ++j) {
                if (KK <= cum + h[j]) { cc = lane * 8 + j; ll = cum; break; }
                cum += h[j];
            }
        }
        const int srcl = __ffs(__ballot_sync(FULLMASK, has)) - 1;
        c1    = __shfl_sync(FULLMASK, cc, srcl);
        less1 = __shfl_sync(FULLMASK, ll, srcl);
    }

    // ---- Pass B (fused): compact ALL items with exponent <= c1 into cand as
    // d^2-keys (u64: (d2bits<<10)|idx) AND build the level-2 histogram (next
    // 8 mantissa bits) for exponent == c1. Replaces old passes B and C. ----
    #pragma unroll
    for (int j = 0; j < 8; ++j) hist[wid][lane * 8 + j] = 0;
    __syncwarp();
    unsigned int cnt = 0;
    #pragma unroll 4
    for (int j = 0; j < 16; ++j) {
        const int    q  = lane + 32 * j;
        const float4 p  = s4loc[q];
        const int    t0 = 2 * q;
        unsigned int v0, v1;
        D2BITS(t0,     p.x, p.y, v0);
        D2BITS(t0 + 1, p.z, p.w, v1);

        const unsigned int e0 = v0 >> 23;
        if (e0 == c1) atomicAdd(&hist[wid][(v0 >> 15) & 0xFFu], 1u);
        bool         sel = (e0 <= c1);
        unsigned int msk = __ballot_sync(FULLMASK, sel);
        if (sel) {
            unsigned int pos = cnt + __popc(msk & ((1u << lane) - 1u));
            if (pos < CAND_CAP)
                cand[wid][pos] =
                    ((unsigned long long)v0 << 10) | (unsigned)t0;
        }
        cnt += __popc(msk);

        const unsigned int e1 = v1 >> 23;
        if (e1 == c1) atomicAdd(&hist[wid][(v1 >> 15) & 0xFFu], 1u);
        sel = (e1 <= c1);
        msk = __ballot_sync(FULLMASK, sel);
        if (sel) {
            unsigned int pos = cnt + __popc(msk & ((1u << lane) - 1u));
            if (pos < CAND_CAP)
                cand[wid][pos] =
                    ((unsigned long long)v1 << 10) | (unsigned)(t0 + 1);
        }
        cnt += __popc(msk);
    }
    const unsigned int mc = min(cnt, (unsigned)CAND_CAP);
    __syncwarp();

    // ---- Level-2 cutoff -> 16-bit prefix P; +1 sub-bin guard band captures
    // every sqrt-rounding tie at the rank-50 boundary. ----
    unsigned int Pp1;
    {
        const unsigned int K2 = KK - less1;                // >= 1
        unsigned int h[8], s = 0;
        #pragma unroll
        for (int j = 0; j < 8; ++j) { h[j] = hist[wid][lane * 8 + j]; s += h[j]; }
        unsigned int incl = s;
        #pragma unroll
        for (int o = 1; o < 32; o <<= 1) {
            unsigned int x = __shfl_up_sync(FULLMASK, incl, o);
            if (lane >= o) incl += x;
        }
        const unsigned int e   = incl - s;
        const bool         has = (e < K2 && K2 <= incl);
        unsigned int pp = 0;
        if (has) {
            unsigned int cum = e;
            #pragma unroll
            for (int j = 0; j < 8; ++j) {
                if (K2 <= cum + h[j]) { pp = (c1 << 8) | (lane * 8 + j); break; }
                cum += h[j];
            }
        }
        const int srcl = __ffs(__ballot_sync(FULLMASK, has)) - 1;
        Pp1 = __shfl_sync(FULLMASK, pp, srcl) + 1;
    }

    // ---- In-place filter over the candidate buffer (~mc/32 iterations):
    // keep prefix <= Pp1, sqrt survivors, rewrite as the exact jax ordering
    // key (bits(d)<<10)|idx (ties break to lower index like lax.top_k).
    // Safe in-place: __ballot_sync converges the warp after all reads of an
    // iteration, and write positions never exceed already-read indices. ----
    unsigned int m = 0;
    for (unsigned int q0 = 0; q0 < mc; q0 += 32) {
        const unsigned int q = q0 + lane;
        unsigned long long key = 0;
        unsigned int v = 0;
        bool sel = false;
        if (q < mc) {
            key = cand[wid][q];
            v   = (unsigned int)(key >> 10);
            sel = ((v >> 15) <= Pp1);
        }
        const unsigned int msk = __ballot_sync(FULLMASK, sel);
        if (sel) {
            float d = __fsqrt_rn(__uint_as_float(v));      // IEEE rn sqrt
            cand[wid][m + __popc(msk & ((1u << lane) - 1u))] =
                ((unsigned long long)__float_as_uint(d) << 10)
                | (unsigned)(key & 1023u);
        }
        m += __popc(msk);
    }
    __syncwarp();

    // ---- Rank-select: keys unique (idx in low bits) -> ranks are a
    // permutation; broadcast-LDS counting loop, no sort, no barriers. ----
    for (unsigned int q = lane; q < m; q += 32) {
        const unsigned long long mykey = cand[wid][q];
        unsigned int rk = 0;
        #pragma unroll 4
        for (unsigned int t = 0; t < m; ++t)
            rk += (cand[wid][t] < mykey);
        if (rk < KK) {
            sdist[wid][rk] = __uint_as_float((unsigned int)(mykey >> 10));
            snbr [wid][rk] = (unsigned int)(mykey & 1023u);
        }
    }
    __syncwarp();

    // ---- edge_index (coalesced, as float). ----
    {
        float* srcp = out + X_ELEMS;
        float* dstp = srcp + E_ELEMS;
        const long long e0 = (long long)node * KK;
        #pragma unroll
        for (int s = lane; s < KK; s += 32) {
            srcp[e0 + s] = (float)node;
            dstp[e0 + s] = (float)(b * NN + (int)snbr[wid][s]);
        }
    }

    // ---- edge_emb[e, :] = dist_e * W + bias; 50 streaming STG.128 rows. ----
    const float4 w4 = __ldg(reinterpret_cast<const float4*>(W) + lane);
    const float4 b4 = __ldg(reinterpret_cast<const float4*>(bias) + lane);
    float4* emb = reinterpret_cast<float4*>(out + X_ELEMS + 2LL * E_ELEMS);
    const long long base = (long long)node * KK;
    #pragma unroll 10
    for (int s = 0; s < KK; ++s) {
        const float dd = sdist[wid][s];
        float4 v;
        v.x = fmaf(dd, w4.x, b4.x);
        v.y = fmaf(dd, w4.y, b4.y);
        v.z = fmaf(dd, w4.z, b4.z);
        v.w = fmaf(dd, w4.w, b4.w);
        __stcs(emb + (base + s) * 32 + lane, v);
    }
    #undef D2BITS
}

extern "C" void kernel_launch(void* const* d_in, const int* in_sizes, int n_in,
                              void* d_out, int out_size)
{
    const float* locs = (const float*)d_in[0];   // [16, 1000, 2]
    const float* xin  = (const float*)d_in[1];   // [16, 1000, 128]
    const float* W    = (const float*)d_in[2];   // [1, 128]
    const float* bias = (const float*)d_in[3];   // [128]
    float* out = (float*)d_out;

    tsp_topk_kernel<<<(BB * NN) / WPB, NTHREADS, 0, 0>>>(locs, xin, W, bias, out);
}

// round 11
// speedup vs baseline: 7.7985x; 1.0252x over previous
#include <cuda_runtime.h>
#include <cstdint>

// Problem constants (fixed by reference setup_inputs)
#define BB   16
#define NN   1000
#define KK   50
#define DD   128
#define NTHREADS 256
#define WPB  8            // warps (= nodes) per block
#define CAND_CAP 224      // per-warp candidate buffer (mc typically ~100)

// Output layout (float32, concatenation of reference outputs):
//   [0,        2048000)   x = init_embeddings
//   [2048000,  2848000)   edge_index row 0 (src)
//   [2848000,  3648000)   edge_index row 1 (dst)
//   [3648000, 106048000)  edge_emb [B*n*k, D]
#define X_ELEMS   (BB * NN * DD)
#define E_ELEMS   (BB * NN * KK)

#define FULLMASK 0xFFFFFFFFu

__global__ __launch_bounds__(NTHREADS, 6)
void tsp_topk_kernel(const float* __restrict__ locs,   // [B, N, 2]
                     const float* __restrict__ xin,    // [B, N, 128]
                     const float* __restrict__ W,      // [128]
                     const float* __restrict__ bias,   // [128]
                     float* __restrict__ out)
{
    __shared__ __align__(16) float2 sloc[1024];            // 8192 B (pads = huge)
    __shared__ unsigned int hist[WPB][256];                // 8 KB (per-warp)
    __shared__ unsigned long long cand[WPB][CAND_CAP];     // 14 KB (per-warp)
    __shared__ float        sdist[WPB][KK];                // 1.6 KB
    __shared__ unsigned int snbr [WPB][KK];                // 1.6 KB

    const int tid  = threadIdx.x;
    const int lane = tid & 31;
    const int wid  = tid >> 5;
    const int b    = blockIdx.x / (NN / WPB);   // 125 blocks per batch, exact
    const int node = blockIdx.x * WPB + wid;    // global node index b*NN + i
    const int i    = node - b * NN;

    // x output first: keeps DRAM busy during the selection phase.
    reinterpret_cast<float4*>(out)[(size_t)node * 32 + lane] =
        reinterpret_cast<const float4*>(xin)[(size_t)node * 32 + lane];

    // Stage this batch's locations (float4 = 2 points/load); pad slots
    // 1000..1023 get huge coords (d^2 ~ 8e18 -> high finite bin, never
    // selected). The only block-wide barrier in the kernel.
    {
        const float4* l4 = reinterpret_cast<const float4*>(locs + (size_t)b * NN * 2);
        float4*       s4 = reinterpret_cast<float4*>(sloc);
        const float4  big = make_float4(2e9f, 2e9f, 2e9f, 2e9f);
        for (int t = tid; t < 512; t += NTHREADS)
            s4[t] = (t < 500) ? l4[t] : big;
    }
    #pragma unroll
    for (int j = 0; j < 8; ++j) hist[wid][lane * 8 + j] = 0;
    __syncthreads();

    const float2 my = sloc[i];
    const float4* s4loc = reinterpret_cast<const float4*>(sloc);

    // d^2 bits (monotone key: d^2 > 0 so float bits order == value order).
    // NO predicates: self (d^2 = 1e-12, the global min) and pads are included
    // and compensated for structurally (rank target KK+1; filter drops self).
    // Matches jax f32 arithmetic exactly (no fma contraction).
    #define D2BITS(px, py, v)                                                 \
        do {                                                                  \
            float dx = my.x - (px);                                           \
            float dy = my.y - (py);                                           \
            float d2 = __fadd_rn(__fadd_rn(__fmul_rn(dx, dx),                 \
                                           __fmul_rn(dy, dy)), 1e-12f);       \
            (v) = __float_as_uint(d2);                                        \
        } while (0)

    // ---- Pass A: level-1 histogram on the 8-bit exponent. Unroll 4 batches
    // LDS.128s for MLP; per-warp hist; match_any aggregation (bins are
    // exponent-concentrated). ----
    #pragma unroll 4
    for (int j = 0; j < 16; ++j) {
        const float4 p = s4loc[lane + 32 * j];
        unsigned int v0, v1;
        D2BITS(p.x, p.y, v0);
        D2BITS(p.z, p.w, v1);
        unsigned int m0 = __match_any_sync(FULLMASK, v0 >> 23);
        if (lane == __ffs(m0) - 1) atomicAdd(&hist[wid][v0 >> 23], __popc(m0));
        unsigned int m1 = __match_any_sync(FULLMASK, v1 >> 23);
        if (lane == __ffs(m1) - 1) atomicAdd(&hist[wid][v1 >> 23], __popc(m1));
    }
    __syncwarp();

    // ---- Level-1 cutoff: bin of the (KK+1)-th smallest value INCLUDING the
    // self point (self is the global min, so rank KK+1 of all == rank KK of
    // the real neighbors; superset property preserved even under ties). ----
    const unsigned int KT = KK + 1;
    unsigned int c1, less1;
    {
        unsigned int h[8], s = 0;
        #pragma unroll
        for (int j = 0; j < 8; ++j) { h[j] = hist[wid][lane * 8 + j]; s += h[j]; }
        unsigned int incl = s;
        #pragma unroll
        for (int o = 1; o < 32; o <<= 1) {
            unsigned int x = __shfl_up_sync(FULLMASK, incl, o);
            if (lane >= o) incl += x;
        }
        const unsigned int e   = incl - s;
        const bool         has = (e < KT && KT <= incl);   // exactly one lane
        unsigned int cc = 0, ll = 0;
        if (has) {
            unsigned int cum = e;
            #pragma unroll
            for (int j = 0; j < 8; ++j) {
                if (KT <= cum + h[j]) { cc = lane * 8 + j; ll = cum; break; }
                cum += h[j];
            }
        }
        const int srcl = __ffs(__ballot_sync(FULLMASK, has)) - 1;
        c1    = __shfl_sync(FULLMASK, cc, srcl);
        less1 = __shfl_sync(FULLMASK, ll, srcl);
    }

    // ---- Pass B (fused): compact ALL items with exponent <= c1 into cand as
    // d^2-keys (u64: (d2bits<<10)|idx) AND build the level-2 histogram (next
    // 8 mantissa bits) for exponent == c1. Predicate-free distances. ----
    #pragma unroll
    for (int j = 0; j < 8; ++j) hist[wid][lane * 8 + j] = 0;
    __syncwarp();
    unsigned int cnt = 0;
    #pragma unroll 4
    for (int j = 0; j < 16; ++j) {
        const int    q  = lane + 32 * j;
        const float4 p  = s4loc[q];
        const int    t0 = 2 * q;
        unsigned int v0, v1;
        D2BITS(p.x, p.y, v0);
        D2BITS(p.z, p.w, v1);

        const unsigned int e0 = v0 >> 23;
        if (e0 == c1) atomicAdd(&hist[wid][(v0 >> 15) & 0xFFu], 1u);
        bool         sel = (e0 <= c1);
        unsigned int msk = __ballot_sync(FULLMASK, sel);
        if (sel) {
            unsigned int pos = cnt + __popc(msk & ((1u << lane) - 1u));
            if (pos < CAND_CAP)
                cand[wid][pos] = ((unsigned long long)v0 << 10) | (unsigned)t0;
        }
        cnt += __popc(msk);

        const unsigned int e1 = v1 >> 23;
        if (e1 == c1) atomicAdd(&hist[wid][(v1 >> 15) & 0xFFu], 1u);
        sel = (e1 <= c1);
        msk = __ballot_sync(FULLMASK, sel);
        if (sel) {
            unsigned int pos = cnt + __popc(msk & ((1u << lane) - 1u));
            if (pos < CAND_CAP)
                cand[wid][pos] = ((unsigned long long)v1 << 10)
                                 | (unsigned)(t0 + 1);
        }
        cnt += __popc(msk);
    }
    const unsigned int mc = min(cnt, (unsigned)CAND_CAP);
    __syncwarp();

    // ---- Level-2 cutoff -> 16-bit prefix P (rank KT within the combined
    // multiset); +1 sub-bin guard band captures every sqrt-rounding tie at
    // the boundary. ----
    unsigned int Pp1;
    {
        const unsigned int K2 = KT - less1;                // >= 1
        unsigned int h[8], s = 0;
        #pragma unroll
        for (int j = 0; j < 8; ++j) { h[j] = hist[wid][lane * 8 + j]; s += h[j]; }
        unsigned int incl = s;
        #pragma unroll
        for (int o = 1; o < 32; o <<= 1) {
            unsigned int x = __shfl_up_sync(FULLMASK, incl, o);
            if (lane >= o) incl += x;
        }
        const unsigned int e   = incl - s;
        const bool         has = (e < K2 && K2 <= incl);
        unsigned int pp = 0;
        if (has) {
            unsigned int cum = e;
            #pragma unroll
            for (int j = 0; j < 8; ++j) {
                if (K2 <= cum + h[j]) { pp = (c1 << 8) | (lane * 8 + j); break; }
                cum += h[j];
            }
        }
        const int srcl = __ffs(__ballot_sync(FULLMASK, has)) - 1;
        Pp1 = __shfl_sync(FULLMASK, pp, srcl) + 1;
    }

    // ---- In-place filter over the candidate buffer (~mc/32 iterations):
    // keep prefix <= Pp1 AND idx != i (drops the self point exactly once),
    // sqrt survivors, rewrite as the exact jax ordering key (bits(d)<<10)|idx
    // (ties break to lower index like lax.top_k). Safe in-place: ballot
    // converges the warp after all reads; writes never pass read frontier. ----
    unsigned int m = 0;
    for (unsigned int q0 = 0; q0 < mc; q0 += 32) {
        const unsigned int q = q0 + lane;
        unsigned long long key = 0;
        unsigned int v = 0;
        bool sel = false;
        if (q < mc) {
            key = cand[wid][q];
            v   = (unsigned int)(key >> 10);
            sel = ((v >> 15) <= Pp1) && ((unsigned)(key & 1023u) != (unsigned)i);
        }
        const unsigned int msk = __ballot_sync(FULLMASK, sel);
        if (sel) {
            float d = __fsqrt_rn(__uint_as_float(v));      // IEEE rn sqrt
            cand[wid][m + __popc(msk & ((1u << lane) - 1u))] =
                ((unsigned long long)__float_as_uint(d) << 10)
                | (unsigned)(key & 1023u);
        }
        m += __popc(msk);
    }
    __syncwarp();

    // ---- Rank-select: keys unique (idx in low bits) -> ranks are a
    // permutation; broadcast-LDS counting loop, no sort, no barriers. ----
    for (unsigned int q = lane; q < m; q += 32) {
        const unsigned long long mykey = cand[wid][q];
        unsigned int rk = 0;
        #pragma unroll 4
        for (unsigned int t = 0; t < m; ++t)
            rk += (cand[wid][t] < mykey);
        if (rk < KK) {
            sdist[wid][rk] = __uint_as_float((unsigned int)(mykey >> 10));
            snbr [wid][rk] = (unsigned int)(mykey & 1023u);
        }
    }
    __syncwarp();

    // W/bias loads issued before the edge_index stores so their L2 latency
    // hides under those stores.
    const float4 w4 = __ldg(reinterpret_cast<const float4*>(W) + lane);
    const float4 b4 = __ldg(reinterpret_cast<const float4*>(bias) + lane);

    // ---- edge_index (coalesced, as float). ----
    {
        float* srcp = out + X_ELEMS;
        float* dstp = srcp + E_ELEMS;
        const long long e0 = (long long)node * KK;
        #pragma unroll
        for (int s = lane; s < KK; s += 32) {
            srcp[e0 + s] = (float)node;
            dstp[e0 + s] = (float)(b * NN + (int)snbr[wid][s]);
        }
    }

    // ---- edge_emb[e, :] = dist_e * W + bias; 50 streaming STG.128 rows. ----
    float4* emb = reinterpret_cast<float4*>(out + X_ELEMS + 2LL * E_ELEMS);
    const long long base = (long long)node * KK;
    #pragma unroll 10
    for (int s = 0; s < KK; ++s) {
        const float dd = sdist[wid][s];
        float4 v;
        v.x = fmaf(dd, w4.x, b4.x);
        v.y = fmaf(dd, w4.y, b4.y);
        v.z = fmaf(dd, w4.z, b4.z);
        v.w = fmaf(dd, w4.w, b4.w);
        __stcs(emb + (base + s) * 32 + lane, v);
    }
    #undef D2BITS
}

extern "C" void kernel_launch(void* const* d_in, const int* in_sizes, int n_in,
                              void* d_out, int out_size)
{
    const float* locs = (const float*)d_in[0];   // [16, 1000, 2]
    const float* xin  = (const float*)d_in[1];   // [16, 1000, 128]
    const float* W    = (const float*)d_in[2];   // [1, 128]
    const float* bias = (const float*)d_in[3];   // [128]
    float* out = (float*)d_out;

    tsp_topk_kernel<<<(BB * NN) / WPB, NTHREADS, 0, 0>>>(locs, xin, W, bias, out);
}